// round 4
// baseline (speedup 1.0000x reference)
#include <cuda_runtime.h>
#include <cstddef>

#define NN 100000
#define NE 1600000
#define DIM 64
#define N_LAYERS 6
#define ZSTR 132   // padded z row stride (floats) -> conflict-free node-strided reads

// ---------------- scratch (no allocations allowed) ----------------
__device__ float g_h1[NN * DIM];
__device__ float g_h2[NN * DIM];
__device__ int   g_deg[NN];
__device__ int   g_off[NN + 1];
__device__ int   g_cur[NN];
__device__ int   g_csrc[NE];

typedef unsigned long long u64;

__device__ __forceinline__ u64 pk2(float x, float y) {
    u64 r; asm("mov.b64 %0,{%1,%2};" : "=l"(r) : "f"(x), "f"(y)); return r;
}
__device__ __forceinline__ void upk2(u64 v, float& x, float& y) {
    asm("mov.b64 {%0,%1},%2;" : "=f"(x), "=f"(y) : "l"(v));
}
__device__ __forceinline__ u64 f2fma(u64 a, u64 b, u64 c) {
    u64 d; asm("fma.rn.f32x2 %0,%1,%2,%3;" : "=l"(d) : "l"(a), "l"(b), "l"(c)); return d;
}
__device__ __forceinline__ u64 relu2(u64 v) {
    float x, y; upk2(v, x, y);
    return pk2(fmaxf(x, 0.f), fmaxf(y, 0.f));
}

// ---------------- CSR build ----------------
__global__ void k_init_deg() {
    int i = blockIdx.x * blockDim.x + threadIdx.x;
    if (i < NN) g_deg[i] = 0;
}

__global__ void k_count(const int* __restrict__ ei) {
    int e = blockIdx.x * blockDim.x + threadIdx.x;
    if (e < NE) {
        int dst = ei[NE + e];
        if ((unsigned)dst < (unsigned)NN) atomicAdd(&g_deg[dst], 1);
    }
}

__global__ void k_scan() {
    __shared__ int sums[1024];
    int t = threadIdx.x;
    const int C = (NN + 1023) / 1024;
    int start = t * C;
    int end = start + C; if (end > NN) end = NN;
    if (start > NN) start = NN;
    int s = 0;
    for (int i = start; i < end; i++) s += g_deg[i];
    sums[t] = s;
    __syncthreads();
    for (int off = 1; off < 1024; off <<= 1) {
        int v = (t >= off) ? sums[t - off] : 0;
        __syncthreads();
        sums[t] += v;
        __syncthreads();
    }
    int base = (t == 0) ? 0 : sums[t - 1];
    for (int i = start; i < end; i++) {
        int d = g_deg[i];
        g_off[i] = base;
        g_cur[i] = base;
        base += d;
    }
    if (t == 1023) g_off[NN] = base;
}

__global__ void k_fill(const int* __restrict__ ei) {
    int e = blockIdx.x * blockDim.x + threadIdx.x;
    if (e < NE) {
        int src = ei[e];
        int dst = ei[NE + e];
        if ((unsigned)dst < (unsigned)NN && (unsigned)src < (unsigned)NN) {
            int p = atomicAdd(&g_cur[dst], 1);
            g_csrc[p] = src;
        }
    }
}

// ---------------- fused SAGE layer ----------------
// Block tile = 128 nodes; warp w owns nodes [tile*128 + 8w, +8).
// Phase 1 (gather): warp-per-node edge loop, unroll 4, lane covers 2 cols;
//                   stage z=[agg|h] rows (ZSTR-padded) in the warp's smem slab.
// Phase 2 (transform): thread = 2 nodes x 8 cols, packed f32x2 accumulators,
//                   weights read as LDS.128 from transposed smem wt=[Wl;Wr].
// No __syncthreads in main loop (warp-private data) -> warps interleave freely.
__global__ __launch_bounds__(512, 2) void k_sage(
    const float* __restrict__ hin_ext, float* __restrict__ hout_ext,
    int sel_in, int sel_out,
    const float* __restrict__ Wl, const float* __restrict__ bl,
    const float* __restrict__ Wr, int do_relu)
{
    extern __shared__ float sm[];
    float* wt   = sm;                 // [128][64]  wt[k*64+j]
    float* bias = sm + 8192;          // [64]
    float* zb   = sm + 8192 + 64;     // 16 warps * 8 nodes * ZSTR

    const float* hin  = (sel_in  == 0) ? hin_ext  : (sel_in  == 1 ? g_h1 : g_h2);
    float*       hout = (sel_out == 0) ? hout_ext : (sel_out == 1 ? g_h1 : g_h2);

    int tid = threadIdx.x;
    for (int i = tid; i < 64 * 64; i += 512) {
        int j = i >> 6, k = i & 63;          // i = j*64 + k
        wt[k * 64 + j]        = Wl[i];
        wt[(64 + k) * 64 + j] = Wr[i];
    }
    if (tid < 64) bias[tid] = bl[tid];
    __syncthreads();

    int w = tid >> 5, lane = tid & 31;
    int nidx = lane >> 3, jidx = lane & 7;
    int j0 = lane * 2;
    float* zw = zb + w * (8 * ZSTR);

    u64 pb0 = pk2(bias[jidx * 8 + 0], bias[jidx * 8 + 1]);
    u64 pb1 = pk2(bias[jidx * 8 + 2], bias[jidx * 8 + 3]);
    u64 pb2 = pk2(bias[jidx * 8 + 4], bias[jidx * 8 + 5]);
    u64 pb3 = pk2(bias[jidx * 8 + 6], bias[jidx * 8 + 7]);

    const int ntiles = (NN + 127) / 128;
    for (int tile = blockIdx.x; tile < ntiles; tile += gridDim.x) {
        int nb = tile * 128 + w * 8;

        // ---- gather 8 nodes into zw ----
        #pragma unroll 1
        for (int ln = 0; ln < 8; ln++) {
            int node = nb + ln;
            if (node >= NN) break;                    // uniform across warp
            int beg = g_off[node], end = g_off[node + 1];
            float ax = -3.4e38f, ay = -3.4e38f;
            int i = beg;
            for (; i + 4 <= end; i += 4) {
                int s0 = g_csrc[i], s1 = g_csrc[i + 1];
                int s2 = g_csrc[i + 2], s3 = g_csrc[i + 3];
                float2 v0 = *(const float2*)(hin + (size_t)s0 * DIM + j0);
                float2 v1 = *(const float2*)(hin + (size_t)s1 * DIM + j0);
                float2 v2 = *(const float2*)(hin + (size_t)s2 * DIM + j0);
                float2 v3 = *(const float2*)(hin + (size_t)s3 * DIM + j0);
                ax = fmaxf(ax, fmaxf(fmaxf(v0.x, v1.x), fmaxf(v2.x, v3.x)));
                ay = fmaxf(ay, fmaxf(fmaxf(v0.y, v1.y), fmaxf(v2.y, v3.y)));
            }
            for (; i < end; i++) {
                int s = g_csrc[i];
                float2 v = *(const float2*)(hin + (size_t)s * DIM + j0);
                ax = fmaxf(ax, v.x);
                ay = fmaxf(ay, v.y);
            }
            if (beg == end) { ax = 0.f; ay = 0.f; }
            float2 hv = *(const float2*)(hin + (size_t)node * DIM + j0);
            *(float2*)&zw[ln * ZSTR + j0]      = make_float2(ax, ay);
            *(float2*)&zw[ln * ZSTR + 64 + j0] = hv;
        }
        __syncwarp();

        // ---- transform: thread computes nodes (n0, n0+1) x cols [8*jidx, +8) ----
        int n0 = nb + 2 * nidx;
        if (n0 < NN) {
            const float* z0 = zw + (2 * nidx) * ZSTR;
            const float* z1 = z0 + ZSTR;
            u64 a00 = pb0, a01 = pb1, a02 = pb2, a03 = pb3;
            u64 a10 = pb0, a11 = pb1, a12 = pb2, a13 = pb3;
            #pragma unroll 8
            for (int k = 0; k < 128; k++) {
                float f0 = z0[k], f1 = z1[k];
                u64 p0 = pk2(f0, f0);
                u64 p1 = pk2(f1, f1);
                ulonglong2 wa = *(const ulonglong2*)&wt[k * 64 + jidx * 8];
                ulonglong2 wb = *(const ulonglong2*)&wt[k * 64 + jidx * 8 + 4];
                a00 = f2fma(p0, wa.x, a00);
                a01 = f2fma(p0, wa.y, a01);
                a02 = f2fma(p0, wb.x, a02);
                a03 = f2fma(p0, wb.y, a03);
                a10 = f2fma(p1, wa.x, a10);
                a11 = f2fma(p1, wa.y, a11);
                a12 = f2fma(p1, wb.x, a12);
                a13 = f2fma(p1, wb.y, a13);
            }
            if (do_relu) {
                a00 = relu2(a00); a01 = relu2(a01); a02 = relu2(a02); a03 = relu2(a03);
                a10 = relu2(a10); a11 = relu2(a11); a12 = relu2(a12); a13 = relu2(a13);
            }
            ulonglong2 s0, s1;
            s0.x = a00; s0.y = a01; s1.x = a02; s1.y = a03;
            *(ulonglong2*)(hout + (size_t)n0 * DIM + jidx * 8)     = s0;
            *(ulonglong2*)(hout + (size_t)n0 * DIM + jidx * 8 + 4) = s1;
            if (n0 + 1 < NN) {
                ulonglong2 t0, t1;
                t0.x = a10; t0.y = a11; t1.x = a12; t1.y = a13;
                *(ulonglong2*)(hout + (size_t)(n0 + 1) * DIM + jidx * 8)     = t0;
                *(ulonglong2*)(hout + (size_t)(n0 + 1) * DIM + jidx * 8 + 4) = t1;
            }
        }
        __syncwarp();
    }
}

// ---------------- launch ----------------
extern "C" void kernel_launch(void* const* d_in, const int* in_sizes, int n_in,
                              void* d_out, int out_size)
{
    const float* x  = (const float*)d_in[0];
    const int*   ei = (const int*)d_in[1];
    const float* Wl = (const float*)d_in[2];
    const float* bl = (const float*)d_in[3];
    const float* Wr = (const float*)d_in[4];
    float*       out = (float*)d_out;

    const int SMEM = (8192 + 64 + 16 * 8 * ZSTR) * 4;   // 100,608 B
    cudaFuncSetAttribute(k_sage, cudaFuncAttributeMaxDynamicSharedMemorySize, SMEM);

    k_init_deg<<<(NN + 255) / 256, 256>>>();
    k_count<<<(NE + 255) / 256, 256>>>(ei);
    k_scan<<<1, 1024>>>();
    k_fill<<<(NE + 255) / 256, 256>>>(ei);

    const int GRID = 296;  // 148 SMs * 2 persistent blocks
    // ping-pong: ext(x) -> g_h1 -> g_h2 -> g_h1 -> g_h2 -> g_h1 -> ext(out)
    int sel_in = 0, sel_out = 1;
    for (int l = 0; l < N_LAYERS; l++) {
        int so = (l == N_LAYERS - 1) ? 0 : sel_out;
        k_sage<<<GRID, 512, SMEM>>>(x, out, sel_in, so,
                                    Wl + (size_t)l * DIM * DIM,
                                    bl + (size_t)l * DIM,
                                    Wr + (size_t)l * DIM * DIM,
                                    (l < N_LAYERS - 1) ? 1 : 0);
        if (l < N_LAYERS - 1) {
            sel_in = sel_out;
            sel_out = (sel_out == 1) ? 2 : 1;
        }
    }
}

// round 6
// speedup vs baseline: 1.0879x; 1.0879x over previous
#include <cuda_runtime.h>
#include <cstddef>

#define NN 100000
#define NE 1600000
#define DIM 64
#define N_LAYERS 6
#define ZSTR 132       // padded z row stride (floats)
#define NUNITS (NN / 8)   // 12500 8-node work units

// ---------------- scratch (no allocations allowed) ----------------
__device__ float g_h1[NN * DIM];
__device__ float g_h2[NN * DIM];
__device__ int   g_deg[NN];
__device__ int   g_off[NN + 1];
__device__ int   g_cur[NN];
__device__ int   g_csrc[NE];
__device__ int   g_tk[8];        // per-layer ticket counters

typedef unsigned long long u64;

__device__ __forceinline__ u64 pk2(float x, float y) {
    u64 r; asm("mov.b64 %0,{%1,%2};" : "=l"(r) : "f"(x), "f"(y)); return r;
}
__device__ __forceinline__ void upk2(u64 v, float& x, float& y) {
    asm("mov.b64 {%0,%1},%2;" : "=f"(x), "=f"(y) : "l"(v));
}
__device__ __forceinline__ u64 f2fma(u64 a, u64 b, u64 c) {
    u64 d; asm("fma.rn.f32x2 %0,%1,%2,%3;" : "=l"(d) : "l"(a), "l"(b), "l"(c)); return d;
}
__device__ __forceinline__ u64 relu2(u64 v) {
    float x, y; upk2(v, x, y);
    return pk2(fmaxf(x, 0.f), fmaxf(y, 0.f));
}
__device__ __forceinline__ float4 max4(float4 a, float4 b) {
    return make_float4(fmaxf(a.x, b.x), fmaxf(a.y, b.y),
                       fmaxf(a.z, b.z), fmaxf(a.w, b.w));
}

// ---------------- CSR build ----------------
__global__ void k_count(const int* __restrict__ ei) {
    int e = blockIdx.x * blockDim.x + threadIdx.x;
    if (e < NE) {
        int dst = ei[NE + e];
        if ((unsigned)dst < (unsigned)NN) atomicAdd(&g_deg[dst], 1);
    }
}

__global__ void k_scan() {
    __shared__ int sums[1024];
    int t = threadIdx.x;
    const int C = (NN + 1023) / 1024;
    int start = t * C;
    int end = start + C; if (end > NN) end = NN;
    if (start > NN) start = NN;
    int s = 0;
    for (int i = start; i < end; i++) s += g_deg[i];
    sums[t] = s;
    __syncthreads();
    for (int off = 1; off < 1024; off <<= 1) {
        int v = (t >= off) ? sums[t - off] : 0;
        __syncthreads();
        sums[t] += v;
        __syncthreads();
    }
    int base = (t == 0) ? 0 : sums[t - 1];
    for (int i = start; i < end; i++) {
        int d = g_deg[i];
        g_off[i] = base;
        g_cur[i] = base;
        base += d;
    }
    if (t == 1023) g_off[NN] = base;
    if (t < 8) g_tk[t] = 0;          // reset layer tickets every run
}

__global__ void k_fill(const int* __restrict__ ei) {
    int e = blockIdx.x * blockDim.x + threadIdx.x;
    if (e < NE) {
        int src = ei[e];
        int dst = ei[NE + e];
        if ((unsigned)dst < (unsigned)NN && (unsigned)src < (unsigned)NN) {
            int p = atomicAdd(&g_cur[dst], 1);
            g_csrc[p] = src;
        }
    }
}

// ---------------- fused SAGE layer ----------------
// Work unit = 8 nodes, pulled by warps via per-layer ticket counter.
// Gather: half-warp per edge (float4 lanes, 16 lanes cover the 64-f row),
//         unroll 4 -> 8 edges in flight per warp; shfl_xor(16) combine.
// Transform: thread = 2 nodes x 8 cols, packed fma.rn.f32x2, weights from
//         transposed smem wt=[Wl;Wr] via LDS.128. Warp-private -> no bar.
__global__ __launch_bounds__(512, 2) void k_sage(
    const float* __restrict__ hin_ext, float* __restrict__ hout_ext,
    int sel_in, int sel_out, int layer,
    const float* __restrict__ Wl, const float* __restrict__ bl,
    const float* __restrict__ Wr, int do_relu)
{
    extern __shared__ float sm[];
    float* wt   = sm;                 // [128][64]
    float* bias = sm + 8192;          // [64]
    float* zb   = sm + 8192 + 64;     // 16 warps * 8 nodes * ZSTR

    const float* hin  = (sel_in  == 0) ? hin_ext  : (sel_in  == 1 ? g_h1 : g_h2);
    float*       hout = (sel_out == 0) ? hout_ext : (sel_out == 1 ? g_h1 : g_h2);

    int tid = threadIdx.x;
    for (int i = tid; i < 64 * 64; i += 512) {
        int j = i >> 6, k = i & 63;
        wt[k * 64 + j]        = Wl[i];
        wt[(64 + k) * 64 + j] = Wr[i];
    }
    if (tid < 64) bias[tid] = bl[tid];
    __syncthreads();

    int w = tid >> 5, lane = tid & 31;
    int half = lane >> 4, c4 = (lane & 15) * 4;   // gather mapping
    int nidx = lane >> 3, jidx = lane & 7;        // transform mapping
    float* zw = zb + w * (8 * ZSTR);

    u64 pb0 = pk2(bias[jidx * 8 + 0], bias[jidx * 8 + 1]);
    u64 pb1 = pk2(bias[jidx * 8 + 2], bias[jidx * 8 + 3]);
    u64 pb2 = pk2(bias[jidx * 8 + 4], bias[jidx * 8 + 5]);
    u64 pb3 = pk2(bias[jidx * 8 + 6], bias[jidx * 8 + 7]);

    while (true) {
        int u;
        if (lane == 0) u = atomicAdd(&g_tk[layer], 1);
        u = __shfl_sync(0xffffffffu, u, 0);
        if (u >= NUNITS) break;
        int nb = u * 8;

        // ---- gather 8 nodes into zw ----
        #pragma unroll 1
        for (int ln = 0; ln < 8; ln++) {
            int node = nb + ln;
            int beg = g_off[node], end = g_off[node + 1];
            float4 m = make_float4(-3.4e38f, -3.4e38f, -3.4e38f, -3.4e38f);
            int i = beg;
            for (; i + 8 <= end; i += 8) {          // 8 edges, 2 per instr
                int s0 = g_csrc[i     + half];
                int s1 = g_csrc[i + 2 + half];
                int s2 = g_csrc[i + 4 + half];
                int s3 = g_csrc[i + 6 + half];
                float4 v0 = *(const float4*)(hin + (size_t)s0 * DIM + c4);
                float4 v1 = *(const float4*)(hin + (size_t)s1 * DIM + c4);
                float4 v2 = *(const float4*)(hin + (size_t)s2 * DIM + c4);
                float4 v3 = *(const float4*)(hin + (size_t)s3 * DIM + c4);
                m = max4(m, max4(max4(v0, v1), max4(v2, v3)));
            }
            for (; i + 2 <= end; i += 2) {          // 2 edges
                int s = g_csrc[i + half];
                float4 v = *(const float4*)(hin + (size_t)s * DIM + c4);
                m = max4(m, v);
            }
            if (i < end) {                           // 1 leftover, both halves dup
                int s = g_csrc[i];
                float4 v = *(const float4*)(hin + (size_t)s * DIM + c4);
                m = max4(m, v);
            }
            // combine halves
            m.x = fmaxf(m.x, __shfl_xor_sync(0xffffffffu, m.x, 16));
            m.y = fmaxf(m.y, __shfl_xor_sync(0xffffffffu, m.y, 16));
            m.z = fmaxf(m.z, __shfl_xor_sync(0xffffffffu, m.z, 16));
            m.w = fmaxf(m.w, __shfl_xor_sync(0xffffffffu, m.w, 16));
            if (beg == end) m = make_float4(0.f, 0.f, 0.f, 0.f);
            if (half == 0) {
                float4 hv = *(const float4*)(hin + (size_t)node * DIM + c4);
                *(float4*)&zw[ln * ZSTR + c4]      = m;
                *(float4*)&zw[ln * ZSTR + 64 + c4] = hv;
            }
        }
        __syncwarp();

        // ---- transform: thread = nodes (n0, n0+1) x cols [8*jidx, +8) ----
        {
            int n0 = nb + 2 * nidx;
            const float* z0 = zw + (2 * nidx) * ZSTR;
            const float* z1 = z0 + ZSTR;
            u64 a00 = pb0, a01 = pb1, a02 = pb2, a03 = pb3;
            u64 a10 = pb0, a11 = pb1, a12 = pb2, a13 = pb3;
            #pragma unroll 8
            for (int k = 0; k < 128; k++) {
                float f0 = z0[k], f1 = z1[k];
                u64 p0 = pk2(f0, f0);
                u64 p1 = pk2(f1, f1);
                ulonglong2 wa = *(const ulonglong2*)&wt[k * 64 + jidx * 8];
                ulonglong2 wb = *(const ulonglong2*)&wt[k * 64 + jidx * 8 + 4];
                a00 = f2fma(p0, wa.x, a00);
                a01 = f2fma(p0, wa.y, a01);
                a02 = f2fma(p0, wb.x, a02);
                a03 = f2fma(p0, wb.y, a03);
                a10 = f2fma(p1, wa.x, a10);
                a11 = f2fma(p1, wa.y, a11);
                a12 = f2fma(p1, wb.x, a12);
                a13 = f2fma(p1, wb.y, a13);
            }
            if (do_relu) {
                a00 = relu2(a00); a01 = relu2(a01); a02 = relu2(a02); a03 = relu2(a03);
                a10 = relu2(a10); a11 = relu2(a11); a12 = relu2(a12); a13 = relu2(a13);
            }
            ulonglong2 s0, s1, t0, t1;
            s0.x = a00; s0.y = a01; s1.x = a02; s1.y = a03;
            t0.x = a10; t0.y = a11; t1.x = a12; t1.y = a13;
            *(ulonglong2*)(hout + (size_t)n0 * DIM + jidx * 8)           = s0;
            *(ulonglong2*)(hout + (size_t)n0 * DIM + jidx * 8 + 4)       = s1;
            *(ulonglong2*)(hout + (size_t)(n0 + 1) * DIM + jidx * 8)     = t0;
            *(ulonglong2*)(hout + (size_t)(n0 + 1) * DIM + jidx * 8 + 4) = t1;
        }
        __syncwarp();
    }
}

// ---------------- launch ----------------
extern "C" void kernel_launch(void* const* d_in, const int* in_sizes, int n_in,
                              void* d_out, int out_size)
{
    const float* x  = (const float*)d_in[0];
    const int*   ei = (const int*)d_in[1];
    const float* Wl = (const float*)d_in[2];
    const float* bl = (const float*)d_in[3];
    const float* Wr = (const float*)d_in[4];
    float*       out = (float*)d_out;

    const int SMEM = (8192 + 64 + 16 * 8 * ZSTR) * 4;   // 100,608 B
    cudaFuncSetAttribute(k_sage, cudaFuncAttributeMaxDynamicSharedMemorySize, SMEM);

    void* deg_ptr = nullptr;
    cudaGetSymbolAddress(&deg_ptr, g_deg);
    cudaMemsetAsync(deg_ptr, 0, NN * sizeof(int));

    k_count<<<(NE + 255) / 256, 256>>>(ei);
    k_scan<<<1, 1024>>>();
    k_fill<<<(NE + 255) / 256, 256>>>(ei);

    const int GRID = 296;  // 148 SMs * 2 persistent blocks
    // ping-pong: ext(x) -> g_h1 -> g_h2 -> g_h1 -> g_h2 -> g_h1 -> ext(out)
    int sel_in = 0, sel_out = 1;
    for (int l = 0; l < N_LAYERS; l++) {
        int so = (l == N_LAYERS - 1) ? 0 : sel_out;
        k_sage<<<GRID, 512, SMEM>>>(x, out, sel_in, so, l,
                                    Wl + (size_t)l * DIM * DIM,
                                    bl + (size_t)l * DIM,
                                    Wr + (size_t)l * DIM * DIM,
                                    (l < N_LAYERS - 1) ? 1 : 0);
        if (l < N_LAYERS - 1) {
            sel_in = sel_out;
            sel_out = (sel_out == 1) ? 2 : 1;
        }
    }
}

// round 8
// speedup vs baseline: 1.1838x; 1.0882x over previous
#include <cuda_runtime.h>
#include <cstddef>

#define NN 100000
#define NE 1600000
#define DIM 64
#define N_LAYERS 6
#define ZSTR 136            // 128 + 8 pad: 4*ZSTR % 32 words == 8 -> conflict-free nidx rows
#define UNIT 16             // nodes per work unit (per warp)
#define NUNITS (NN / UNIT)  // 6250

// ---------------- scratch (no allocations allowed) ----------------
__device__ float g_h1[NN * DIM];
__device__ float g_h2[NN * DIM];
__device__ int   g_deg[NN];
__device__ int   g_off[NN + 1];
__device__ int   g_cur[NN];
__device__ int   g_csrc[NE];
__device__ int   g_tk[8];        // per-layer ticket counters

typedef unsigned long long u64;

__device__ __forceinline__ u64 pk2(float x, float y) {
    u64 r; asm("mov.b64 %0,{%1,%2};" : "=l"(r) : "f"(x), "f"(y)); return r;
}
__device__ __forceinline__ void upk2(u64 v, float& x, float& y) {
    asm("mov.b64 {%0,%1},%2;" : "=f"(x), "=f"(y) : "l"(v));
}
__device__ __forceinline__ u64 f2fma(u64 a, u64 b, u64 c) {
    u64 d; asm("fma.rn.f32x2 %0,%1,%2,%3;" : "=l"(d) : "l"(a), "l"(b), "l"(c)); return d;
}
__device__ __forceinline__ u64 relu2(u64 v) {
    float x, y; upk2(v, x, y);
    return pk2(fmaxf(x, 0.f), fmaxf(y, 0.f));
}
__device__ __forceinline__ float4 max4(float4 a, float4 b) {
    return make_float4(fmaxf(a.x, b.x), fmaxf(a.y, b.y),
                       fmaxf(a.z, b.z), fmaxf(a.w, b.w));
}

// ---------------- CSR build ----------------
__global__ void k_count(const int* __restrict__ ei) {
    int e = blockIdx.x * blockDim.x + threadIdx.x;
    if (e < NE) {
        int dst = ei[NE + e];
        if ((unsigned)dst < (unsigned)NN) atomicAdd(&g_deg[dst], 1);
    }
}

__global__ void k_scan() {
    __shared__ int sums[1024];
    int t = threadIdx.x;
    const int C = (NN + 1023) / 1024;
    int start = t * C;
    int end = start + C; if (end > NN) end = NN;
    if (start > NN) start = NN;
    int s = 0;
    for (int i = start; i < end; i++) s += g_deg[i];
    sums[t] = s;
    __syncthreads();
    for (int off = 1; off < 1024; off <<= 1) {
        int v = (t >= off) ? sums[t - off] : 0;
        __syncthreads();
        sums[t] += v;
        __syncthreads();
    }
    int base = (t == 0) ? 0 : sums[t - 1];
    for (int i = start; i < end; i++) {
        int d = g_deg[i];
        g_off[i] = base;
        g_cur[i] = base;
        base += d;
    }
    if (t == 1023) g_off[NN] = base;
    if (t < 8) g_tk[t] = 0;          // reset layer tickets every replay
}

__global__ void k_fill(const int* __restrict__ ei) {
    int e = blockIdx.x * blockDim.x + threadIdx.x;
    if (e < NE) {
        int src = ei[e];
        int dst = ei[NE + e];
        if ((unsigned)dst < (unsigned)NN && (unsigned)src < (unsigned)NN) {
            int p = atomicAdd(&g_cur[dst], 1);
            g_csrc[p] = src;
        }
    }
}

// ---------------- fused SAGE layer ----------------
// Work unit = 16 nodes, pulled by warps via per-layer ticket counter.
// Gather: half-warp per edge (float4 lanes, 16 lanes cover the 64-f row),
//         unroll 4 -> 8 edges in flight per warp; shfl_xor(16) combine.
// Transform: thread = 4 nodes x 8 cols (16 packed f32x2 accumulators),
//         weights via LDS.128 from transposed smem wt=[Wl;Wr] (amortized
//         over 16 nodes), z via float4 per node per 4-k chunk.
__global__ __launch_bounds__(512, 1) void k_sage(
    const float* __restrict__ hin_ext, float* __restrict__ hout_ext,
    int sel_in, int sel_out, int layer,
    const float* __restrict__ Wl, const float* __restrict__ bl,
    const float* __restrict__ Wr, int do_relu)
{
    extern __shared__ float sm[];
    float* wt   = sm;                 // [128][64]
    float* bias = sm + 8192;          // [64]
    float* zb   = sm + 8192 + 64;     // 16 warps * UNIT * ZSTR

    const float* hin  = (sel_in  == 0) ? hin_ext  : (sel_in  == 1 ? g_h1 : g_h2);
    float*       hout = (sel_out == 0) ? hout_ext : (sel_out == 1 ? g_h1 : g_h2);

    int tid = threadIdx.x;
    for (int i = tid; i < 64 * 64; i += 512) {
        int j = i >> 6, k = i & 63;
        wt[k * 64 + j]        = Wl[i];
        wt[(64 + k) * 64 + j] = Wr[i];
    }
    if (tid < 64) bias[tid] = bl[tid];
    __syncthreads();

    int w = tid >> 5, lane = tid & 31;
    int half = lane >> 4, c4 = (lane & 15) * 4;   // gather mapping
    int nidx = lane >> 3, jidx = lane & 7;        // transform mapping
    float* zw = zb + w * (UNIT * ZSTR);

    u64 pb0 = pk2(bias[jidx * 8 + 0], bias[jidx * 8 + 1]);
    u64 pb1 = pk2(bias[jidx * 8 + 2], bias[jidx * 8 + 3]);
    u64 pb2 = pk2(bias[jidx * 8 + 4], bias[jidx * 8 + 5]);
    u64 pb3 = pk2(bias[jidx * 8 + 6], bias[jidx * 8 + 7]);

    while (true) {
        int u;
        if (lane == 0) u = atomicAdd(&g_tk[layer], 1);
        u = __shfl_sync(0xffffffffu, u, 0);
        if (u >= NUNITS) break;
        int nb = u * UNIT;

        // ---- gather UNIT nodes into zw ----
        #pragma unroll 1
        for (int ln = 0; ln < UNIT; ln++) {
            int node = nb + ln;
            int beg = g_off[node], end = g_off[node + 1];
            float4 m = make_float4(-3.4e38f, -3.4e38f, -3.4e38f, -3.4e38f);
            int i = beg;
            for (; i + 8 <= end; i += 8) {          // 8 edges, 2 per instr
                int s0 = g_csrc[i     + half];
                int s1 = g_csrc[i + 2 + half];
                int s2 = g_csrc[i + 4 + half];
                int s3 = g_csrc[i + 6 + half];
                float4 v0 = *(const float4*)(hin + (size_t)s0 * DIM + c4);
                float4 v1 = *(const float4*)(hin + (size_t)s1 * DIM + c4);
                float4 v2 = *(const float4*)(hin + (size_t)s2 * DIM + c4);
                float4 v3 = *(const float4*)(hin + (size_t)s3 * DIM + c4);
                m = max4(m, max4(max4(v0, v1), max4(v2, v3)));
            }
            for (; i + 2 <= end; i += 2) {          // 2 edges
                int s = g_csrc[i + half];
                float4 v = *(const float4*)(hin + (size_t)s * DIM + c4);
                m = max4(m, v);
            }
            if (i < end) {                           // 1 leftover, both halves dup
                int s = g_csrc[i];
                float4 v = *(const float4*)(hin + (size_t)s * DIM + c4);
                m = max4(m, v);
            }
            m.x = fmaxf(m.x, __shfl_xor_sync(0xffffffffu, m.x, 16));
            m.y = fmaxf(m.y, __shfl_xor_sync(0xffffffffu, m.y, 16));
            m.z = fmaxf(m.z, __shfl_xor_sync(0xffffffffu, m.z, 16));
            m.w = fmaxf(m.w, __shfl_xor_sync(0xffffffffu, m.w, 16));
            if (beg == end) m = make_float4(0.f, 0.f, 0.f, 0.f);
            if (half == 0) {
                float4 hv = *(const float4*)(hin + (size_t)node * DIM + c4);
                *(float4*)&zw[ln * ZSTR + c4]      = m;
                *(float4*)&zw[ln * ZSTR + 64 + c4] = hv;
            }
        }
        __syncwarp();

        // ---- transform: thread = nodes [nb+4*nidx, +4) x cols [8*jidx, +8) ----
        {
            const float* zr = zw + (4 * nidx) * ZSTR;
            u64 a0[4], a1[4], a2[4], a3[4];
            #pragma unroll
            for (int i = 0; i < 4; i++) { a0[i] = pb0; a1[i] = pb1; a2[i] = pb2; a3[i] = pb3; }

            #pragma unroll 2
            for (int k4 = 0; k4 < 128; k4 += 4) {
                float4 zv[4];
                #pragma unroll
                for (int i = 0; i < 4; i++)
                    zv[i] = *(const float4*)&zr[i * ZSTR + k4];
                #pragma unroll
                for (int kk = 0; kk < 4; kk++) {
                    int k = k4 + kk;
                    ulonglong2 wa = *(const ulonglong2*)&wt[k * 64 + jidx * 8];
                    ulonglong2 wb = *(const ulonglong2*)&wt[k * 64 + jidx * 8 + 4];
                    #pragma unroll
                    for (int i = 0; i < 4; i++) {
                        float f = (kk == 0) ? zv[i].x : (kk == 1) ? zv[i].y
                                : (kk == 2) ? zv[i].z : zv[i].w;
                        u64 p = pk2(f, f);
                        a0[i] = f2fma(p, wa.x, a0[i]);
                        a1[i] = f2fma(p, wa.y, a1[i]);
                        a2[i] = f2fma(p, wb.x, a2[i]);
                        a3[i] = f2fma(p, wb.y, a3[i]);
                    }
                }
            }
            #pragma unroll
            for (int i = 0; i < 4; i++) {
                u64 v0 = a0[i], v1 = a1[i], v2 = a2[i], v3 = a3[i];
                if (do_relu) { v0 = relu2(v0); v1 = relu2(v1); v2 = relu2(v2); v3 = relu2(v3); }
                int node = nb + 4 * nidx + i;
                ulonglong2 s0, s1;
                s0.x = v0; s0.y = v1; s1.x = v2; s1.y = v3;
                *(ulonglong2*)(hout + (size_t)node * DIM + jidx * 8)     = s0;
                *(ulonglong2*)(hout + (size_t)node * DIM + jidx * 8 + 4) = s1;
            }
        }
        __syncwarp();
    }
}

// ---------------- launch ----------------
extern "C" void kernel_launch(void* const* d_in, const int* in_sizes, int n_in,
                              void* d_out, int out_size)
{
    const float* x  = (const float*)d_in[0];
    const int*   ei = (const int*)d_in[1];
    const float* Wl = (const float*)d_in[2];
    const float* bl = (const float*)d_in[3];
    const float* Wr = (const float*)d_in[4];
    float*       out = (float*)d_out;

    const int SMEM = (8192 + 64 + 16 * UNIT * ZSTR) * 4;   // 172,288 B
    cudaFuncSetAttribute(k_sage, cudaFuncAttributeMaxDynamicSharedMemorySize, SMEM);

    void* deg_ptr = nullptr;
    cudaGetSymbolAddress(&deg_ptr, g_deg);
    cudaMemsetAsync(deg_ptr, 0, NN * sizeof(int));

    k_count<<<(NE + 255) / 256, 256>>>(ei);
    k_scan<<<1, 1024>>>();
    k_fill<<<(NE + 255) / 256, 256>>>(ei);

    const int GRID = 148;  // 1 persistent block per SM (smem-bound)
    // ping-pong: ext(x) -> g_h1 -> g_h2 -> g_h1 -> g_h2 -> g_h1 -> ext(out)
    int sel_in = 0, sel_out = 1;
    for (int l = 0; l < N_LAYERS; l++) {
        int so = (l == N_LAYERS - 1) ? 0 : sel_out;
        k_sage<<<GRID, 512, SMEM>>>(x, out, sel_in, so, l,
                                    Wl + (size_t)l * DIM * DIM,
                                    bl + (size_t)l * DIM,
                                    Wr + (size_t)l * DIM * DIM,
                                    (l < N_LAYERS - 1) ? 1 : 0);
        if (l < N_LAYERS - 1) {
            sel_in = sel_out;
            sel_out = (sel_out == 1) ? 2 : 1;
        }
    }
}

// round 9
// speedup vs baseline: 1.3663x; 1.1541x over previous
#include <cuda_runtime.h>
#include <cstddef>

#define NN 100000
#define NE 1600000
#define DIM 64
#define N_LAYERS 6
#define ZSTR 68             // agg-only z row: 64 + 4 pad
#define UNIT 16             // nodes per work unit (per warp)
#define NUNITS (NN / UNIT)  // 6250
#define NWARPS 18
#define NTHREADS (NWARPS * 32)   // 576

// ---------------- scratch (no allocations allowed) ----------------
__device__ float g_h1[NN * DIM];
__device__ float g_h2[NN * DIM];
__device__ int   g_deg[NN];
__device__ int   g_off[NN + 1];
__device__ int   g_cur[NN];
__device__ int   g_csrc[NE];
__device__ int   g_tk[8];        // per-layer ticket counters

typedef unsigned long long u64;

__device__ __forceinline__ u64 pk2(float x, float y) {
    u64 r; asm("mov.b64 %0,{%1,%2};" : "=l"(r) : "f"(x), "f"(y)); return r;
}
__device__ __forceinline__ void upk2(u64 v, float& x, float& y) {
    asm("mov.b64 {%0,%1},%2;" : "=f"(x), "=f"(y) : "l"(v));
}
__device__ __forceinline__ u64 f2fma(u64 a, u64 b, u64 c) {
    u64 d; asm("fma.rn.f32x2 %0,%1,%2,%3;" : "=l"(d) : "l"(a), "l"(b), "l"(c)); return d;
}
__device__ __forceinline__ u64 relu2(u64 v) {
    float x, y; upk2(v, x, y);
    return pk2(fmaxf(x, 0.f), fmaxf(y, 0.f));
}
__device__ __forceinline__ float4 max4(float4 a, float4 b) {
    return make_float4(fmaxf(a.x, b.x), fmaxf(a.y, b.y),
                       fmaxf(a.z, b.z), fmaxf(a.w, b.w));
}

// ---------------- CSR build ----------------
__global__ void k_count(const int* __restrict__ ei) {
    int e = blockIdx.x * blockDim.x + threadIdx.x;
    if (e < NE) {
        int dst = ei[NE + e];
        if ((unsigned)dst < (unsigned)NN) atomicAdd(&g_deg[dst], 1);
    }
}

__global__ void k_scan() {
    __shared__ int sums[1024];
    int t = threadIdx.x;
    const int C = (NN + 1023) / 1024;
    int start = t * C;
    int end = start + C; if (end > NN) end = NN;
    if (start > NN) start = NN;
    int s = 0;
    for (int i = start; i < end; i++) s += g_deg[i];
    sums[t] = s;
    __syncthreads();
    for (int off = 1; off < 1024; off <<= 1) {
        int v = (t >= off) ? sums[t - off] : 0;
        __syncthreads();
        sums[t] += v;
        __syncthreads();
    }
    int base = (t == 0) ? 0 : sums[t - 1];
    for (int i = start; i < end; i++) {
        int d = g_deg[i];
        g_off[i] = base;
        g_cur[i] = base;
        base += d;
    }
    if (t == 1023) g_off[NN] = base;
    if (t < 8) g_tk[t] = 0;          // reset layer tickets every replay
}

__global__ void k_fill(const int* __restrict__ ei) {
    int e = blockIdx.x * blockDim.x + threadIdx.x;
    if (e < NE) {
        int src = ei[e];
        int dst = ei[NE + e];
        if ((unsigned)dst < (unsigned)NN && (unsigned)src < (unsigned)NN) {
            int p = atomicAdd(&g_cur[dst], 1);
            g_csrc[p] = src;
        }
    }
}

// ---------------- fused SAGE layer ----------------
// Work unit = 16 nodes, pulled by warps via per-layer ticket counter.
// Gather: DUAL-STREAM — two nodes' edge loops interleaved, half-warp per
//         edge (float4 lanes), 8 LDG.128 (16 edges) in flight; shfl_xor(16).
//         Only agg goes to smem (ZSTR=68).
// Transform: thread = 4 nodes x 8 cols (16 packed f32x2 accumulators).
//         k<64: z = agg from smem. k>=64: z = h read directly from gmem
//         (uniform per quarter-warp -> broadcast, L1-resident rows).
__global__ __launch_bounds__(NTHREADS, 1) void k_sage(
    const float* __restrict__ hin_ext, float* __restrict__ hout_ext,
    int sel_in, int sel_out, int layer,
    const float* __restrict__ Wl, const float* __restrict__ bl,
    const float* __restrict__ Wr, int do_relu)
{
    extern __shared__ float sm[];
    float* wt   = sm;                 // [128][64]
    float* bias = sm + 8192;          // [64]
    float* zb   = sm + 8192 + 64;     // NWARPS * UNIT * ZSTR (agg only)

    const float* hin  = (sel_in  == 0) ? hin_ext  : (sel_in  == 1 ? g_h1 : g_h2);
    float*       hout = (sel_out == 0) ? hout_ext : (sel_out == 1 ? g_h1 : g_h2);

    int tid = threadIdx.x;
    for (int i = tid; i < 64 * 64; i += NTHREADS) {
        int j = i >> 6, k = i & 63;
        wt[k * 64 + j]        = Wl[i];
        wt[(64 + k) * 64 + j] = Wr[i];
    }
    if (tid < 64) bias[tid] = bl[tid];
    __syncthreads();

    int w = tid >> 5, lane = tid & 31;
    int half = lane >> 4, c4 = (lane & 15) * 4;   // gather mapping
    int nidx = lane >> 3, jidx = lane & 7;        // transform mapping
    float* zw = zb + w * (UNIT * ZSTR);

    u64 pb0 = pk2(bias[jidx * 8 + 0], bias[jidx * 8 + 1]);
    u64 pb1 = pk2(bias[jidx * 8 + 2], bias[jidx * 8 + 3]);
    u64 pb2 = pk2(bias[jidx * 8 + 4], bias[jidx * 8 + 5]);
    u64 pb3 = pk2(bias[jidx * 8 + 6], bias[jidx * 8 + 7]);

    while (true) {
        int u;
        if (lane == 0) u = atomicAdd(&g_tk[layer], 1);
        u = __shfl_sync(0xffffffffu, u, 0);
        if (u >= NUNITS) break;
        int nb = u * UNIT;

        // ---- gather UNIT nodes (agg only) into zw, two streams at a time ----
        #pragma unroll 1
        for (int ln = 0; ln < UNIT; ln += 2) {
            int i0 = g_off[nb + ln],     e0 = g_off[nb + ln + 1];
            int i1 = g_off[nb + ln + 1], e1 = g_off[nb + ln + 2];
            bool emp0 = (i0 == e0), emp1 = (i1 == e1);
            float4 m0 = make_float4(-3.4e38f, -3.4e38f, -3.4e38f, -3.4e38f);
            float4 m1 = m0;

            // joint main loop: 16 edges (8 per stream) in flight
            while (i0 + 8 <= e0 && i1 + 8 <= e1) {
                int a0 = g_csrc[i0     + half], a1 = g_csrc[i0 + 2 + half];
                int a2 = g_csrc[i0 + 4 + half], a3 = g_csrc[i0 + 6 + half];
                int b0 = g_csrc[i1     + half], b1 = g_csrc[i1 + 2 + half];
                int b2 = g_csrc[i1 + 4 + half], b3 = g_csrc[i1 + 6 + half];
                float4 va0 = *(const float4*)(hin + (size_t)a0 * DIM + c4);
                float4 va1 = *(const float4*)(hin + (size_t)a1 * DIM + c4);
                float4 va2 = *(const float4*)(hin + (size_t)a2 * DIM + c4);
                float4 va3 = *(const float4*)(hin + (size_t)a3 * DIM + c4);
                float4 vb0 = *(const float4*)(hin + (size_t)b0 * DIM + c4);
                float4 vb1 = *(const float4*)(hin + (size_t)b1 * DIM + c4);
                float4 vb2 = *(const float4*)(hin + (size_t)b2 * DIM + c4);
                float4 vb3 = *(const float4*)(hin + (size_t)b3 * DIM + c4);
                m0 = max4(m0, max4(max4(va0, va1), max4(va2, va3)));
                m1 = max4(m1, max4(max4(vb0, vb1), max4(vb2, vb3)));
                i0 += 8; i1 += 8;
            }
            // stream-0 tail
            for (; i0 + 8 <= e0; i0 += 8) {
                int a0 = g_csrc[i0     + half], a1 = g_csrc[i0 + 2 + half];
                int a2 = g_csrc[i0 + 4 + half], a3 = g_csrc[i0 + 6 + half];
                float4 v0 = *(const float4*)(hin + (size_t)a0 * DIM + c4);
                float4 v1 = *(const float4*)(hin + (size_t)a1 * DIM + c4);
                float4 v2 = *(const float4*)(hin + (size_t)a2 * DIM + c4);
                float4 v3 = *(const float4*)(hin + (size_t)a3 * DIM + c4);
                m0 = max4(m0, max4(max4(v0, v1), max4(v2, v3)));
            }
            for (; i0 + 2 <= e0; i0 += 2) {
                int s = g_csrc[i0 + half];
                m0 = max4(m0, *(const float4*)(hin + (size_t)s * DIM + c4));
            }
            if (i0 < e0) {
                int s = g_csrc[i0];
                m0 = max4(m0, *(const float4*)(hin + (size_t)s * DIM + c4));
            }
            // stream-1 tail
            for (; i1 + 8 <= e1; i1 += 8) {
                int b0 = g_csrc[i1     + half], b1 = g_csrc[i1 + 2 + half];
                int b2 = g_csrc[i1 + 4 + half], b3 = g_csrc[i1 + 6 + half];
                float4 v0 = *(const float4*)(hin + (size_t)b0 * DIM + c4);
                float4 v1 = *(const float4*)(hin + (size_t)b1 * DIM + c4);
                float4 v2 = *(const float4*)(hin + (size_t)b2 * DIM + c4);
                float4 v3 = *(const float4*)(hin + (size_t)b3 * DIM + c4);
                m1 = max4(m1, max4(max4(v0, v1), max4(v2, v3)));
            }
            for (; i1 + 2 <= e1; i1 += 2) {
                int s = g_csrc[i1 + half];
                m1 = max4(m1, *(const float4*)(hin + (size_t)s * DIM + c4));
            }
            if (i1 < e1) {
                int s = g_csrc[i1];
                m1 = max4(m1, *(const float4*)(hin + (size_t)s * DIM + c4));
            }
            // combine halves
            m0.x = fmaxf(m0.x, __shfl_xor_sync(0xffffffffu, m0.x, 16));
            m0.y = fmaxf(m0.y, __shfl_xor_sync(0xffffffffu, m0.y, 16));
            m0.z = fmaxf(m0.z, __shfl_xor_sync(0xffffffffu, m0.z, 16));
            m0.w = fmaxf(m0.w, __shfl_xor_sync(0xffffffffu, m0.w, 16));
            m1.x = fmaxf(m1.x, __shfl_xor_sync(0xffffffffu, m1.x, 16));
            m1.y = fmaxf(m1.y, __shfl_xor_sync(0xffffffffu, m1.y, 16));
            m1.z = fmaxf(m1.z, __shfl_xor_sync(0xffffffffu, m1.z, 16));
            m1.w = fmaxf(m1.w, __shfl_xor_sync(0xffffffffu, m1.w, 16));
            if (emp0) m0 = make_float4(0.f, 0.f, 0.f, 0.f);
            if (emp1) m1 = make_float4(0.f, 0.f, 0.f, 0.f);
            if (half == 0) {
                *(float4*)&zw[ln * ZSTR + c4]       = m0;
                *(float4*)&zw[(ln + 1) * ZSTR + c4] = m1;
            }
        }
        __syncwarp();

        // ---- transform: thread = nodes [nb+4*nidx, +4) x cols [8*jidx, +8) ----
        {
            int n0 = nb + 4 * nidx;
            const float* zr = zw + (4 * nidx) * ZSTR;
            u64 a0[4], a1[4], a2[4], a3[4];
            #pragma unroll
            for (int i = 0; i < 4; i++) { a0[i] = pb0; a1[i] = pb1; a2[i] = pb2; a3[i] = pb3; }

            // half 1: k in [0,64) -> z = agg from smem
            #pragma unroll 2
            for (int k4 = 0; k4 < 64; k4 += 4) {
                float4 zv[4];
                #pragma unroll
                for (int i = 0; i < 4; i++)
                    zv[i] = *(const float4*)&zr[i * ZSTR + k4];
                #pragma unroll
                for (int kk = 0; kk < 4; kk++) {
                    int k = k4 + kk;
                    ulonglong2 wa = *(const ulonglong2*)&wt[k * 64 + jidx * 8];
                    ulonglong2 wb = *(const ulonglong2*)&wt[k * 64 + jidx * 8 + 4];
                    #pragma unroll
                    for (int i = 0; i < 4; i++) {
                        float f = (kk == 0) ? zv[i].x : (kk == 1) ? zv[i].y
                                : (kk == 2) ? zv[i].z : zv[i].w;
                        u64 p = pk2(f, f);
                        a0[i] = f2fma(p, wa.x, a0[i]);
                        a1[i] = f2fma(p, wa.y, a1[i]);
                        a2[i] = f2fma(p, wb.x, a2[i]);
                        a3[i] = f2fma(p, wb.y, a3[i]);
                    }
                }
            }
            // half 2: k in [64,128) -> z = h direct from gmem (broadcast lanes)
            #pragma unroll 2
            for (int k4 = 0; k4 < 64; k4 += 4) {
                float4 zv[4];
                #pragma unroll
                for (int i = 0; i < 4; i++)
                    zv[i] = *(const float4*)(hin + (size_t)(n0 + i) * DIM + k4);
                #pragma unroll
                for (int kk = 0; kk < 4; kk++) {
                    int k = 64 + k4 + kk;
                    ulonglong2 wa = *(const ulonglong2*)&wt[k * 64 + jidx * 8];
                    ulonglong2 wb = *(const ulonglong2*)&wt[k * 64 + jidx * 8 + 4];
                    #pragma unroll
                    for (int i = 0; i < 4; i++) {
                        float f = (kk == 0) ? zv[i].x : (kk == 1) ? zv[i].y
                                : (kk == 2) ? zv[i].z : zv[i].w;
                        u64 p = pk2(f, f);
                        a0[i] = f2fma(p, wa.x, a0[i]);
                        a1[i] = f2fma(p, wa.y, a1[i]);
                        a2[i] = f2fma(p, wb.x, a2[i]);
                        a3[i] = f2fma(p, wb.y, a3[i]);
                    }
                }
            }
            #pragma unroll
            for (int i = 0; i < 4; i++) {
                u64 v0 = a0[i], v1 = a1[i], v2 = a2[i], v3 = a3[i];
                if (do_relu) { v0 = relu2(v0); v1 = relu2(v1); v2 = relu2(v2); v3 = relu2(v3); }
                int node = n0 + i;
                ulonglong2 s0, s1;
                s0.x = v0; s0.y = v1; s1.x = v2; s1.y = v3;
                *(ulonglong2*)(hout + (size_t)node * DIM + jidx * 8)     = s0;
                *(ulonglong2*)(hout + (size_t)node * DIM + jidx * 8 + 4) = s1;
            }
        }
        __syncwarp();
    }
}

// ---------------- launch ----------------
extern "C" void kernel_launch(void* const* d_in, const int* in_sizes, int n_in,
                              void* d_out, int out_size)
{
    const float* x  = (const float*)d_in[0];
    const int*   ei = (const int*)d_in[1];
    const float* Wl = (const float*)d_in[2];
    const float* bl = (const float*)d_in[3];
    const float* Wr = (const float*)d_in[4];
    float*       out = (float*)d_out;

    const int SMEM = (8192 + 64 + NWARPS * UNIT * ZSTR) * 4;   // 111,360 B
    cudaFuncSetAttribute(k_sage, cudaFuncAttributeMaxDynamicSharedMemorySize, SMEM);

    void* deg_ptr = nullptr;
    cudaGetSymbolAddress(&deg_ptr, g_deg);
    cudaMemsetAsync(deg_ptr, 0, NN * sizeof(int));

    k_count<<<(NE + 255) / 256, 256>>>(ei);
    k_scan<<<1, 1024>>>();
    k_fill<<<(NE + 255) / 256, 256>>>(ei);

    const int GRID = 148;  // 1 persistent block per SM
    // ping-pong: ext(x) -> g_h1 -> g_h2 -> g_h1 -> g_h2 -> g_h1 -> ext(out)
    int sel_in = 0, sel_out = 1;
    for (int l = 0; l < N_LAYERS; l++) {
        int so = (l == N_LAYERS - 1) ? 0 : sel_out;
        k_sage<<<GRID, NTHREADS, SMEM>>>(x, out, sel_in, so, l,
                                         Wl + (size_t)l * DIM * DIM,
                                         bl + (size_t)l * DIM,
                                         Wr + (size_t)l * DIM * DIM,
                                         (l < N_LAYERS - 1) ? 1 : 0);
        if (l < N_LAYERS - 1) {
            sel_in = sel_out;
            sel_out = (sel_out == 1) ? 2 : 1;
        }
    }
}